// round 15
// baseline (speedup 1.0000x reference)
#include <cuda_runtime.h>
#include <cuda_fp16.h>
#include <cstdint>

#define Bn 4
#define Tn 2048
#define Cn 1024
#define Hn 16
#define DHn 64
#define SCALE_F 0.125f
#define KP 2048                 // row stride of fp16 A/B buffers (hi half used)
#define C3 3072                 // qkv plane row stride
#define NCH 32
#define LCH 64

// ---------------- scratch (__device__ globals) ------------------------------
__device__ __half g_qkvh[Bn * Tn * C3];       // qkv hi plane [8192,3072]
__device__ __half g_qkvl[Bn * Tn * C3];       // qkv lo plane
__device__ __half g_xhl[Bn * Tn * KP];        // x    -> [hi|-]
__device__ __half g_ahl[Bn * Tn * KP];        // attn -> [hi|-]
__device__ __half g_wqkv[3 * Cn * KP];        // Wqkv -> [hi|-]
__device__ __half g_wout[Cn * KP];            // Wout -> [hi|-]
__device__ float  g_kv[Bn * Hn * NCH * DHn * DHn];
__device__ float  g_s [Bn * Hn * NCH * DHn * DHn];

// ---------------- helpers ---------------------------------------------------
__device__ __forceinline__ uint32_t smem_u32(const void* p) {
    uint32_t a;
    asm("{ .reg .u64 t; cvta.to.shared.u64 t, %1; cvt.u32.u64 %0, t; }" : "=r"(a) : "l"(p));
    return a;
}
__device__ __forceinline__ void ldsm_x4(uint32_t& r0, uint32_t& r1, uint32_t& r2,
                                        uint32_t& r3, uint32_t addr) {
    asm volatile("ldmatrix.sync.aligned.m8n8.x4.shared.b16 {%0,%1,%2,%3}, [%4];"
                 : "=r"(r0), "=r"(r1), "=r"(r2), "=r"(r3) : "r"(addr));
}
__device__ __forceinline__ void ldsm_x4_t(uint32_t& r0, uint32_t& r1, uint32_t& r2,
                                          uint32_t& r3, uint32_t addr) {
    asm volatile("ldmatrix.sync.aligned.m8n8.x4.trans.shared.b16 {%0,%1,%2,%3}, [%4];"
                 : "=r"(r0), "=r"(r1), "=r"(r2), "=r"(r3) : "r"(addr));
}
__device__ __forceinline__ void mma16816(float& d0, float& d1, float& d2, float& d3,
                                         uint32_t a0, uint32_t a1, uint32_t a2, uint32_t a3,
                                         uint32_t b0, uint32_t b1) {
    asm volatile(
        "mma.sync.aligned.m16n8k16.row.col.f32.f16.f16.f32 "
        "{%0,%1,%2,%3},{%4,%5,%6,%7},{%8,%9},{%0,%1,%2,%3};"
        : "+f"(d0), "+f"(d1), "+f"(d2), "+f"(d3)
        : "r"(a0), "r"(a1), "r"(a2), "r"(a3), "r"(b0), "r"(b1));
}

__device__ __forceinline__ uint2 hi4(float4 v) {
    __half2 h0 = __floats2half2_rn(v.x, v.y);
    __half2 h1 = __floats2half2_rn(v.z, v.w);
    uint2 r; r.x = *(uint32_t*)&h0; r.y = *(uint32_t*)&h1;
    return r;
}
__device__ __forceinline__ void split2(float a, float b, uint32_t& hi, uint32_t& lo) {
    __half2 h = __floats2half2_rn(a, b);
    float ra = a - __half2float(__low2half(h));
    float rb = b - __half2float(__high2half(h));
    __half2 l = __floats2half2_rn(ra, rb);
    hi = *(uint32_t*)&h; lo = *(uint32_t*)&l;
}

__device__ __forceinline__ uint32_t offR(int row, int d) {        // 128B rows
    return (uint32_t)(row * 128 + (((d >> 3) ^ (row & 7)) << 4) + ((d & 7) << 1));
}
__device__ __forceinline__ uint32_t off128(int row, int kpos) {   // 256B rows
    return (uint32_t)(row * 256 + (((kpos >> 3) ^ (row & 7)) << 4) + ((kpos & 7) << 1));
}

// ---------------------------------------------------------------------------
// fp32 -> fp16 hi-only pack into rows of stride 2K (second half unused)
// ---------------------------------------------------------------------------
__global__ void __launch_bounds__(256) cvt_hi(const float* __restrict__ in,
                                              __half* __restrict__ out,
                                              int R, int K) {
    int idx = blockIdx.x * 256 + threadIdx.x;
    int per_row = K >> 2;
    if (idx >= R * per_row) return;
    int r = idx / per_row;
    int k = (idx - r * per_row) << 2;
    float4 v = *(const float4*)(in + (long)r * K + k);
    *(uint2*)(out + (long)r * (2 * K) + k) = hi4(v);
}

// ---------------------------------------------------------------------------
// HMMA fp16 NT GEMM: C = A·B^T (Kdim runtime, row stride KP).
// Epilogue: f16out=0 -> fp32 to C; f16out=1 -> hi/lo fp16 planes Ch/Cl.
// 128x128 CTA, 4 warps 64x64, 3-stage cp.async, 2 CTAs/SM.
// ---------------------------------------------------------------------------
#define KC 64
#define STG_B 32768
#define NSTG 3

__global__ void __launch_bounds__(128, 2) gemm_hmma(const __half* __restrict__ A,
                                                    const __half* __restrict__ Bw,
                                                    float* __restrict__ C,
                                                    __half* __restrict__ Ch,
                                                    __half* __restrict__ Cl,
                                                    int ldc, int Kdim, int f16out) {
    extern __shared__ __align__(1024) char dsm[];
    const uint32_t smem0 = smem_u32(dsm);
    const int NIT = Kdim >> 6;

    const int tid = threadIdx.x;
    const int wid = tid >> 5, lid = tid & 31;
    const int bm = blockIdx.y * 128;
    const int bn = blockIdx.x * 128;
    const int wm = (wid & 1) * 64;
    const int wn = (wid >> 1) * 64;

    const char* gsrc[16];
    uint32_t sdst[16];
#pragma unroll
    for (int i = 0; i < 16; i++) {
        int c = tid + i * 128;
        int row = c >> 3;
        int ck = c & 7;
        const __half* base =
            (row < 128) ? (A + (long)(bm + row) * KP)
                        : (Bw + (long)(bn + row - 128) * KP);
        gsrc[i] = (const char*)base + ck * 16;
        sdst[i] = row * 128 + ((ck ^ (row & 7)) * 16);
    }

    auto load_stage = [&](int j) {
        uint32_t sb = smem0 + (j % NSTG) * STG_B;
        long koff = (long)j * (KC * 2);
#pragma unroll
        for (int i = 0; i < 16; i++) {
            asm volatile("cp.async.cg.shared.global [%0], [%1], 16;"
                         :: "r"(sb + sdst[i]), "l"(gsrc[i] + koff));
        }
        asm volatile("cp.async.commit_group;" ::: "memory");
    };

    float acc[4][8][4];
#pragma unroll
    for (int mt = 0; mt < 4; mt++)
#pragma unroll
        for (int nt = 0; nt < 8; nt++)
#pragma unroll
            for (int q = 0; q < 4; q++) acc[mt][nt][q] = 0.f;

    load_stage(0);
    load_stage(1);

    const int mat = lid >> 3, r8 = lid & 7;
    const int arow = wm + (mat & 1) * 8 + r8;
    const int brow = 128 + wn + (mat >> 1) * 8 + r8;
    const int akh = mat >> 1;
    const int bkh = mat & 1;

    for (int it = 0; it < NIT; it++) {
        if (it + 1 < NIT) {
            asm volatile("cp.async.wait_group 1;" ::: "memory");
        } else {
            asm volatile("cp.async.wait_group 0;" ::: "memory");
        }
        __syncthreads();
        if (it + 2 < NIT) load_stage(it + 2);

        uint32_t sb = smem0 + (it % NSTG) * STG_B;
#pragma unroll
        for (int ks = 0; ks < 4; ks++) {
            uint32_t af[4][4], bf[4][4];
#pragma unroll
            for (int mt = 0; mt < 4; mt++) {
                int row = arow + mt * 16;
                int ck = (ks * 2 + akh) ^ (row & 7);
                ldsm_x4(af[mt][0], af[mt][1], af[mt][2], af[mt][3],
                        sb + row * 128 + ck * 16);
            }
#pragma unroll
            for (int nb = 0; nb < 4; nb++) {
                int row = brow + nb * 16;
                int ck = (ks * 2 + bkh) ^ (row & 7);
                ldsm_x4(bf[nb][0], bf[nb][1], bf[nb][2], bf[nb][3],
                        sb + row * 128 + ck * 16);
            }
#pragma unroll
            for (int mt = 0; mt < 4; mt++)
#pragma unroll
                for (int nt = 0; nt < 8; nt++) {
                    uint32_t b0 = bf[nt >> 1][(nt & 1) * 2 + 0];
                    uint32_t b1 = bf[nt >> 1][(nt & 1) * 2 + 1];
                    mma16816(acc[mt][nt][0], acc[mt][nt][1],
                             acc[mt][nt][2], acc[mt][nt][3],
                             af[mt][0], af[mt][1], af[mt][2], af[mt][3], b0, b1);
                }
        }
    }

    const int erow = lid >> 2;
    const int ecol = (lid & 3) * 2;
    if (!f16out) {
#pragma unroll
        for (int mt = 0; mt < 4; mt++) {
#pragma unroll
            for (int nt = 0; nt < 8; nt++) {
                long r0 = bm + wm + mt * 16 + erow;
                long col = bn + wn + nt * 8 + ecol;
                float2 v0 = {acc[mt][nt][0], acc[mt][nt][1]};
                float2 v1 = {acc[mt][nt][2], acc[mt][nt][3]};
                *(float2*)(C + r0 * ldc + col)       = v0;
                *(float2*)(C + (r0 + 8) * ldc + col) = v1;
            }
        }
    } else {
#pragma unroll
        for (int mt = 0; mt < 4; mt++) {
#pragma unroll
            for (int nt = 0; nt < 8; nt++) {
                long r0 = bm + wm + mt * 16 + erow;
                long col = bn + wn + nt * 8 + ecol;
                uint32_t hi0, lo0, hi1, lo1;
                split2(acc[mt][nt][0], acc[mt][nt][1], hi0, lo0);
                split2(acc[mt][nt][2], acc[mt][nt][3], hi1, lo1);
                *(uint32_t*)(Ch + r0 * ldc + col)       = hi0;
                *(uint32_t*)(Cl + r0 * ldc + col)       = lo0;
                *(uint32_t*)(Ch + (r0 + 8) * ldc + col) = hi1;
                *(uint32_t*)(Cl + (r0 + 8) * ldc + col) = lo1;
            }
        }
    }
}

// ---------------------------------------------------------------------------
// Attention stage A (HMMA, 2-term): KV_c = [Kh|Kl]^T · [Vh|Vh]  (k=128)
// Reads pre-split fp16 planes; no conversion math.
// ---------------------------------------------------------------------------
__global__ void __launch_bounds__(256) chunk_kv_hmma(const __half* __restrict__ qh,
                                                     const __half* __restrict__ ql,
                                                     float* __restrict__ kv) {
    __shared__ __align__(1024) char sm2[24576];
    const uint32_t smb = smem_u32(sm2);

    const int c = blockIdx.x, bh = blockIdx.y;
    const int b = bh / Hn, h = bh % Hn;
    const int tid = threadIdx.x;
    const int wid = tid >> 5, lid = tid & 31;
    const long t0 = (long)c * LCH;

    const __half* bhp = qh + ((long)b * Tn) * C3 + Cn + h * DHn;  // K hi
    const __half* blp = ql + ((long)b * Tn) * C3 + Cn + h * DHn;  // K lo

#pragma unroll
    for (int p = tid; p < 1024; p += 256) {
        int t = p >> 4;
        int d = (p & 15) << 2;
        long ro = (t0 + t) * C3 + d;
        uint2 kh = *(const uint2*)(bhp + ro);
        uint2 kl = *(const uint2*)(blp + ro);
        uint2 vh = *(const uint2*)(bhp + ro + Cn);
        *(uint2*)(sm2 + offR(t, d))      = kh;
        *(uint2*)(sm2 + offR(t + 64, d)) = kl;
        *(uint2*)(sm2 + 16384 + offR(t, d)) = vh;
    }
    __syncthreads();

    const int wm = (wid & 3) * 16;
    const int wn = (wid >> 2) * 32;
    const int mat = lid >> 3, r8 = lid & 7;
    const int akr = (mat >> 1) * 8 + r8;
    const int amc = (wm >> 3) + (mat & 1);
    const int tkr = (mat & 1) * 8 + r8;
    const int tnc = mat >> 1;

    float acc[4][4];
#pragma unroll
    for (int nt = 0; nt < 4; nt++)
#pragma unroll
        for (int q = 0; q < 4; q++) acc[nt][q] = 0.f;

#pragma unroll
    for (int ks = 0; ks < 8; ks++) {
        int blk = ks >> 2;
        int kl2 = (ks & 3) * 16;
        int abase = blk ? 64 : 0;

        uint32_t af[4], bf[2][4];
        {
            int row = abase + kl2 + akr;
            ldsm_x4_t(af[0], af[1], af[2], af[3],
                      smb + (uint32_t)(row * 128 + ((amc ^ (row & 7)) << 4)));
        }
#pragma unroll
        for (int nb = 0; nb < 2; nb++) {
            int row = kl2 + tkr;
            int cc = (wn >> 3) + nb * 2 + tnc;
            ldsm_x4_t(bf[nb][0], bf[nb][1], bf[nb][2], bf[nb][3],
                      smb + 16384 + (uint32_t)(row * 128 + ((cc ^ (row & 7)) << 4)));
        }
#pragma unroll
        for (int nt = 0; nt < 4; nt++)
            mma16816(acc[nt][0], acc[nt][1], acc[nt][2], acc[nt][3],
                     af[0], af[1], af[2], af[3],
                     bf[nt >> 1][(nt & 1) * 2], bf[nt >> 1][(nt & 1) * 2 + 1]);
    }

    const int r = lid >> 2;
    const int cq = (lid & 3) * 2;
    float* outp = kv + ((long)(bh * NCH + c) << 12);
#pragma unroll
    for (int nt = 0; nt < 4; nt++) {
        int col = wn + nt * 8 + cq;
        float2 v0 = {acc[nt][0], acc[nt][1]};
        float2 v1 = {acc[nt][2], acc[nt][3]};
        *(float2*)(outp + (wm + r) * DHn + col)     = v0;
        *(float2*)(outp + (wm + r + 8) * DHn + col) = v1;
    }
}

// ---------------------------------------------------------------------------
// Attention stage B: exclusive prefix over chunks. grid (B*H, 16).
// ---------------------------------------------------------------------------
__global__ void __launch_bounds__(256) prefix_kernel(const float* __restrict__ kv,
                                                     float* __restrict__ s) {
    const int bh = blockIdx.x;
    const int idx = blockIdx.y * 256 + threadIdx.x;
    float S = 0.f;
#pragma unroll 4
    for (int c = 0; c < NCH; c++) {
        long base = (long)(bh * NCH + c) << 12;
        s[base + idx] = S;
        S += kv[base + idx];
    }
}

// ---------------------------------------------------------------------------
// Attention stage C (HMMA fp16 2-term); reads pre-split planes; O hi-only out.
// ---------------------------------------------------------------------------
#define QP_OFF 0
#define KP_OFF 16384
#define PP_OFF 16384
#define VP_OFF 32768
#define SP_OFF 49152
#define ATT_SMEM 65536

__global__ void __launch_bounds__(256, 2) attn_hmma(const __half* __restrict__ qh,
                                                    const __half* __restrict__ ql,
                                                    const float* __restrict__ s,
                                                    __half* __restrict__ ahl) {
    extern __shared__ __align__(1024) char asmem[];
    char* sm = asmem;
    const uint32_t smb = smem_u32(asmem);

    const int c = blockIdx.x, bh = blockIdx.y;
    const int b = bh / Hn, h = bh % Hn;
    const int tid = threadIdx.x;
    const int wid = tid >> 5, lid = tid & 31;
    const long t0 = (long)c * LCH;

    const __half* bhp = qh + ((long)b * Tn) * C3 + h * DHn;
    const __half* blp = ql + ((long)b * Tn) * C3 + h * DHn;
    const float* sbase = s + ((long)(bh * NCH + c) << 12);

#pragma unroll
    for (int p = tid; p < 1024; p += 256) {
        int t = p >> 4;
        int d = (p & 15) << 2;
        long ro = (t0 + t) * C3 + d;
        uint2 qh4 = *(const uint2*)(bhp + ro);
        uint2 ql4 = *(const uint2*)(blp + ro);
        uint2 kh4 = *(const uint2*)(bhp + ro + Cn);
        uint2 vh4 = *(const uint2*)(bhp + ro + 2 * Cn);
        float4 s4 = *(const float4*)(sbase + t * DHn + d);

        *(uint2*)(sm + QP_OFF + off128(t, d))      = qh4;
        *(uint2*)(sm + QP_OFF + off128(t, 64 + d)) = ql4;

        *(uint2*)(sm + KP_OFF + off128(t, d))      = kh4;
        *(uint2*)(sm + KP_OFF + off128(t, 64 + d)) = kh4;

        *(uint2*)(sm + VP_OFF + offR(t, d))      = vh4;
        *(uint2*)(sm + VP_OFF + offR(t + 64, d)) = vh4;

        uint2 sh = hi4(s4);
        *(uint2*)(sm + SP_OFF + offR(t, d))      = sh;
        *(uint2*)(sm + SP_OFF + offR(t + 64, d)) = sh;
    }
    __syncthreads();

    const int wm = (wid & 3) * 16;
    const int wn = (wid >> 2) * 32;
    const int mat = lid >> 3, r8 = lid & 7;
    const int arow = wm + (mat & 1) * 8 + r8;
    const int akh = mat >> 1;
    const int bro = (mat >> 1) * 8 + r8;
    const int bkh = mat & 1;
    const int tkr = (mat & 1) * 8 + r8;
    const int tnc = mat >> 1;

    // ---- P = Q K^T (k = 128) ----
    float pac[4][4];
#pragma unroll
    for (int nt = 0; nt < 4; nt++)
#pragma unroll
        for (int q = 0; q < 4; q++) pac[nt][q] = 0.f;

#pragma unroll
    for (int ks = 0; ks < 8; ks++) {
        uint32_t af[4], bf[2][4];
        ldsm_x4(af[0], af[1], af[2], af[3],
                smb + QP_OFF + (uint32_t)(arow * 256 + (((ks * 2 + akh) ^ (arow & 7)) << 4)));
#pragma unroll
        for (int nb = 0; nb < 2; nb++) {
            int row = wn + nb * 16 + bro;
            ldsm_x4(bf[nb][0], bf[nb][1], bf[nb][2], bf[nb][3],
                    smb + KP_OFF + (uint32_t)(row * 256 + (((ks * 2 + bkh) ^ (row & 7)) << 4)));
        }
#pragma unroll
        for (int nt = 0; nt < 4; nt++)
            mma16816(pac[nt][0], pac[nt][1], pac[nt][2], pac[nt][3],
                     af[0], af[1], af[2], af[3],
                     bf[nt >> 1][(nt & 1) * 2], bf[nt >> 1][(nt & 1) * 2 + 1]);
    }

    __syncthreads();   // Kp fully consumed before Pp overwrite

    {
        const int r = lid >> 2;
        const int cq = (lid & 3) * 2;
#pragma unroll
        for (int nt = 0; nt < 4; nt++) {
            int col = wn + nt * 8 + cq;
            int row0 = wm + r, row1 = wm + r + 8;
            float c0 = (col     <= row0) ? pac[nt][0] : 0.f;
            float c1 = (col + 1 <= row0) ? pac[nt][1] : 0.f;
            float c2 = (col     <= row1) ? pac[nt][2] : 0.f;
            float c3 = (col + 1 <= row1) ? pac[nt][3] : 0.f;
            uint32_t hi, lo;
            split2(c0, c1, hi, lo);
            *(uint32_t*)(sm + PP_OFF + off128(row0, col))      = hi;
            *(uint32_t*)(sm + PP_OFF + off128(row0, 64 + col)) = lo;
            split2(c2, c3, hi, lo);
            *(uint32_t*)(sm + PP_OFF + off128(row1, col))      = hi;
            *(uint32_t*)(sm + PP_OFF + off128(row1, 64 + col)) = lo;
        }
    }
    __syncthreads();

    // ---- O = [Pp | Qp] x [Vh ; Sh]  (k = 256) ----
    float oac[4][4];
#pragma unroll
    for (int nt = 0; nt < 4; nt++)
#pragma unroll
        for (int q = 0; q < 4; q++) oac[nt][q] = 0.f;

#pragma unroll
    for (int ks = 0; ks < 16; ks++) {
        uint32_t abase = (ks < 8) ? (smb + PP_OFF) : (smb + QP_OFF);
        int ksl = ks & 7;
        uint32_t bbase = (ks < 8) ? (smb + VP_OFF) : (smb + SP_OFF);
        int krow = ksl * 16 + tkr;

        uint32_t af[4], bf[2][4];
        ldsm_x4(af[0], af[1], af[2], af[3],
                abase + (uint32_t)(arow * 256 + (((ksl * 2 + akh) ^ (arow & 7)) << 4)));
#pragma unroll
        for (int nb = 0; nb < 2; nb++) {
            int cc = (wn >> 3) + nb * 2 + tnc;
            ldsm_x4_t(bf[nb][0], bf[nb][1], bf[nb][2], bf[nb][3],
                      bbase + (uint32_t)(krow * 128 + ((cc ^ (krow & 7)) << 4)));
        }
#pragma unroll
        for (int nt = 0; nt < 4; nt++)
            mma16816(oac[nt][0], oac[nt][1], oac[nt][2], oac[nt][3],
                     af[0], af[1], af[2], af[3],
                     bf[nt >> 1][(nt & 1) * 2], bf[nt >> 1][(nt & 1) * 2 + 1]);
    }

    // ---- scale, fp16 hi-only write to g_ahl ----
    {
        const int r = lid >> 2;
        const int cq = (lid & 3) * 2;
        __half* abase = ahl + ((long)b * Tn + t0) * KP + h * DHn;
#pragma unroll
        for (int nt = 0; nt < 4; nt++) {
            int dg = wn + nt * 8 + cq;
            __half2 h0 = __floats2half2_rn(oac[nt][0] * SCALE_F, oac[nt][1] * SCALE_F);
            __half2 h1 = __floats2half2_rn(oac[nt][2] * SCALE_F, oac[nt][3] * SCALE_F);
            *(uint32_t*)(abase + (long)(wm + r) * KP + dg)     = *(uint32_t*)&h0;
            *(uint32_t*)(abase + (long)(wm + r + 8) * KP + dg) = *(uint32_t*)&h1;
        }
    }
}

// ---------------------------------------------------------------------------
extern "C" void kernel_launch(void* const* d_in, const int* in_sizes, int n_in,
                              void* d_out, int out_size) {
    const float* x    = (const float*)d_in[0];
    const float* Wqkv = (const float*)d_in[1];
    const float* Wout = (const float*)d_in[2];
    float* out = (float*)d_out;

    float *kv_p, *s_p;
    __half *qh_p, *ql_p, *xhl_p, *ahl_p, *wq_p, *wo_p;
    cudaGetSymbolAddress((void**)&qh_p, g_qkvh);
    cudaGetSymbolAddress((void**)&ql_p, g_qkvl);
    cudaGetSymbolAddress((void**)&kv_p, g_kv);
    cudaGetSymbolAddress((void**)&s_p, g_s);
    cudaGetSymbolAddress((void**)&xhl_p, g_xhl);
    cudaGetSymbolAddress((void**)&ahl_p, g_ahl);
    cudaGetSymbolAddress((void**)&wq_p, g_wqkv);
    cudaGetSymbolAddress((void**)&wo_p, g_wout);

    const int M = Bn * Tn;
    const int gemm_smem = NSTG * STG_B;          // 98304
    cudaFuncSetAttribute(gemm_hmma, cudaFuncAttributeMaxDynamicSharedMemorySize, gemm_smem);
    cudaFuncSetAttribute(attn_hmma, cudaFuncAttributeMaxDynamicSharedMemorySize, ATT_SMEM);

    // hi-only converts
    cvt_hi<<<(M * Cn / 4 + 255) / 256, 256>>>(x, xhl_p, M, Cn);
    cvt_hi<<<(3 * Cn * Cn / 4 + 255) / 256, 256>>>(Wqkv, wq_p, 3 * Cn, Cn);
    cvt_hi<<<(Cn * Cn / 4 + 255) / 256, 256>>>(Wout, wo_p, Cn, Cn);

    // GEMM1: qkv(h,l) = split(xh @ Wqkv_h^T)   K'=1024, fp16 dual-plane out
    {
        dim3 grid(3 * Cn / 128, M / 128);
        gemm_hmma<<<grid, 128, gemm_smem>>>(xhl_p, wq_p, nullptr,
                                            qh_p, ql_p, C3, Cn, 1);
    }

    // attention: HMMA chunk KV -> prefix -> HMMA per-chunk output
    {
        dim3 gkv(NCH, Bn * Hn);
        chunk_kv_hmma<<<gkv, 256>>>(qh_p, ql_p, kv_p);
        dim3 gpre(Bn * Hn, 16);
        prefix_kernel<<<gpre, 256>>>(kv_p, s_p);
        attn_hmma<<<gkv, 256, ATT_SMEM>>>(qh_p, ql_p, s_p, ahl_p);
    }

    // GEMM2: out = attn_h @ Wout_h^T  (K'=1024, fp32 out)
    {
        dim3 grid(Cn / 128, M / 128);
        gemm_hmma<<<grid, 128, gemm_smem>>>(ahl_p, wo_p, out,
                                            nullptr, nullptr, Cn, Cn, 0);
    }
}

// round 16
// speedup vs baseline: 1.0716x; 1.0716x over previous
#include <cuda_runtime.h>
#include <cuda_fp16.h>
#include <cstdint>

#define Bn 4
#define Tn 2048
#define Cn 1024
#define Hn 16
#define DHn 64
#define SCALE_F 0.125f
#define KP 2048                 // row stride of fp16 buffers (hi half used)
#define NCH 32
#define LCH 64

// ---------------- scratch (__device__ globals) ------------------------------
__device__ float  g_qkv[Bn * Tn * 3 * Cn];    // [8192,3072] fp32
__device__ __half g_xhl[Bn * Tn * KP];        // x    -> [hi|-]
__device__ __half g_ahl[Bn * Tn * KP];        // attn -> [hi|-]
__device__ __half g_wqkv[3 * Cn * KP];        // Wqkv -> [hi|-]
__device__ __half g_wout[Cn * KP];            // Wout -> [hi|-]
__device__ float  g_kv[Bn * Hn * NCH * DHn * DHn];
__device__ float  g_s [Bn * Hn * NCH * DHn * DHn];

// ---------------- helpers ---------------------------------------------------
__device__ __forceinline__ uint32_t smem_u32(const void* p) {
    uint32_t a;
    asm("{ .reg .u64 t; cvta.to.shared.u64 t, %1; cvt.u32.u64 %0, t; }" : "=r"(a) : "l"(p));
    return a;
}
__device__ __forceinline__ void ldsm_x4(uint32_t& r0, uint32_t& r1, uint32_t& r2,
                                        uint32_t& r3, uint32_t addr) {
    asm volatile("ldmatrix.sync.aligned.m8n8.x4.shared.b16 {%0,%1,%2,%3}, [%4];"
                 : "=r"(r0), "=r"(r1), "=r"(r2), "=r"(r3) : "r"(addr));
}
__device__ __forceinline__ void ldsm_x4_t(uint32_t& r0, uint32_t& r1, uint32_t& r2,
                                          uint32_t& r3, uint32_t addr) {
    asm volatile("ldmatrix.sync.aligned.m8n8.x4.trans.shared.b16 {%0,%1,%2,%3}, [%4];"
                 : "=r"(r0), "=r"(r1), "=r"(r2), "=r"(r3) : "r"(addr));
}
__device__ __forceinline__ void mma16816(float& d0, float& d1, float& d2, float& d3,
                                         uint32_t a0, uint32_t a1, uint32_t a2, uint32_t a3,
                                         uint32_t b0, uint32_t b1) {
    asm volatile(
        "mma.sync.aligned.m16n8k16.row.col.f32.f16.f16.f32 "
        "{%0,%1,%2,%3},{%4,%5,%6,%7},{%8,%9},{%0,%1,%2,%3};"
        : "+f"(d0), "+f"(d1), "+f"(d2), "+f"(d3)
        : "r"(a0), "r"(a1), "r"(a2), "r"(a3), "r"(b0), "r"(b1));
}

__device__ __forceinline__ void split4(float4 v, uint2& hh, uint2& ll) {
    __half2 h0 = __floats2half2_rn(v.x, v.y);
    __half2 h1 = __floats2half2_rn(v.z, v.w);
    float rx = v.x - __half2float(__low2half(h0));
    float ry = v.y - __half2float(__high2half(h0));
    float rz = v.z - __half2float(__low2half(h1));
    float rw = v.w - __half2float(__high2half(h1));
    __half2 l0 = __floats2half2_rn(rx, ry);
    __half2 l1 = __floats2half2_rn(rz, rw);
    hh.x = *(uint32_t*)&h0; hh.y = *(uint32_t*)&h1;
    ll.x = *(uint32_t*)&l0; ll.y = *(uint32_t*)&l1;
}
__device__ __forceinline__ uint2 hi4(float4 v) {
    __half2 h0 = __floats2half2_rn(v.x, v.y);
    __half2 h1 = __floats2half2_rn(v.z, v.w);
    uint2 r; r.x = *(uint32_t*)&h0; r.y = *(uint32_t*)&h1;
    return r;
}
__device__ __forceinline__ void split2(float a, float b, uint32_t& hi, uint32_t& lo) {
    __half2 h = __floats2half2_rn(a, b);
    float ra = a - __half2float(__low2half(h));
    float rb = b - __half2float(__high2half(h));
    __half2 l = __floats2half2_rn(ra, rb);
    hi = *(uint32_t*)&h; lo = *(uint32_t*)&l;
}

__device__ __forceinline__ uint32_t offR(int row, int d) {        // 128B rows
    return (uint32_t)(row * 128 + (((d >> 3) ^ (row & 7)) << 4) + ((d & 7) << 1));
}
__device__ __forceinline__ uint32_t off128(int row, int kpos) {   // 256B rows
    return (uint32_t)(row * 256 + (((kpos >> 3) ^ (row & 7)) << 4) + ((kpos & 7) << 1));
}

// ---------------------------------------------------------------------------
// Merged hi-only convert of x, Wqkv, Wout (one launch).
// ranges (in float4 units): x 2M, wqkv 768K, wout 256K -> 3M total
// ---------------------------------------------------------------------------
#define NX  (Bn * Tn * Cn / 4)          // 2,097,152
#define NWQ (3 * Cn * Cn / 4)           // 786,432
#define NWO (Cn * Cn / 4)               // 262,144

__global__ void __launch_bounds__(256) cvt_all(const float* __restrict__ x,
                                               const float* __restrict__ wq,
                                               const float* __restrict__ wo,
                                               __half* __restrict__ xo,
                                               __half* __restrict__ wqo,
                                               __half* __restrict__ woo) {
    int idx = blockIdx.x * 256 + threadIdx.x;
    const float* in;
    __half* out;
    if (idx < NX) {
        in = x; out = xo;
    } else if (idx < NX + NWQ) {
        idx -= NX; in = wq; out = wqo;
    } else {
        idx -= NX + NWQ;
        if (idx >= NWO) return;
        in = wo; out = woo;
    }
    int per_row = Cn >> 2;
    int r = idx / per_row;
    int k = (idx - r * per_row) << 2;
    float4 v = *(const float4*)(in + (long)r * Cn + k);
    *(uint2*)(out + (long)r * KP + k) = hi4(v);
}

// ---------------------------------------------------------------------------
// HMMA fp16 NT GEMM (R14 config): Kdim/ldc runtime, fp32 out.
// 128x128 CTA, 4 warps 64x64, 3-stage cp.async, 2 CTAs/SM.
// grid.x spans M, grid.y spans N (raster order: N-major -> better L2 for B).
// ---------------------------------------------------------------------------
#define KC 64
#define STG_B 32768
#define NSTG 3

__global__ void __launch_bounds__(128, 2) gemm_hmma(const __half* __restrict__ A,
                                                    const __half* __restrict__ Bw,
                                                    float* __restrict__ C,
                                                    int ldc, int Kdim) {
    extern __shared__ __align__(1024) char dsm[];
    const uint32_t smem0 = smem_u32(dsm);
    const int NIT = Kdim >> 6;

    const int tid = threadIdx.x;
    const int wid = tid >> 5, lid = tid & 31;
    const int bm = blockIdx.x * 128;
    const int bn = blockIdx.y * 128;
    const int wm = (wid & 1) * 64;
    const int wn = (wid >> 1) * 64;

    const char* gsrc[16];
    uint32_t sdst[16];
#pragma unroll
    for (int i = 0; i < 16; i++) {
        int c = tid + i * 128;
        int row = c >> 3;
        int ck = c & 7;
        const __half* base =
            (row < 128) ? (A + (long)(bm + row) * KP)
                        : (Bw + (long)(bn + row - 128) * KP);
        gsrc[i] = (const char*)base + ck * 16;
        sdst[i] = row * 128 + ((ck ^ (row & 7)) * 16);
    }

    auto load_stage = [&](int j) {
        uint32_t sb = smem0 + (j % NSTG) * STG_B;
        long koff = (long)j * (KC * 2);
#pragma unroll
        for (int i = 0; i < 16; i++) {
            asm volatile("cp.async.cg.shared.global [%0], [%1], 16;"
                         :: "r"(sb + sdst[i]), "l"(gsrc[i] + koff));
        }
        asm volatile("cp.async.commit_group;" ::: "memory");
    };

    float acc[4][8][4];
#pragma unroll
    for (int mt = 0; mt < 4; mt++)
#pragma unroll
        for (int nt = 0; nt < 8; nt++)
#pragma unroll
            for (int q = 0; q < 4; q++) acc[mt][nt][q] = 0.f;

    load_stage(0);
    load_stage(1);

    const int mat = lid >> 3, r8 = lid & 7;
    const int arow = wm + (mat & 1) * 8 + r8;
    const int brow = 128 + wn + (mat >> 1) * 8 + r8;
    const int akh = mat >> 1;
    const int bkh = mat & 1;

    for (int it = 0; it < NIT; it++) {
        if (it + 1 < NIT) {
            asm volatile("cp.async.wait_group 1;" ::: "memory");
        } else {
            asm volatile("cp.async.wait_group 0;" ::: "memory");
        }
        __syncthreads();
        if (it + 2 < NIT) load_stage(it + 2);

        uint32_t sb = smem0 + (it % NSTG) * STG_B;
#pragma unroll
        for (int ks = 0; ks < 4; ks++) {
            uint32_t af[4][4], bf[4][4];
#pragma unroll
            for (int mt = 0; mt < 4; mt++) {
                int row = arow + mt * 16;
                int ck = (ks * 2 + akh) ^ (row & 7);
                ldsm_x4(af[mt][0], af[mt][1], af[mt][2], af[mt][3],
                        sb + row * 128 + ck * 16);
            }
#pragma unroll
            for (int nb = 0; nb < 4; nb++) {
                int row = brow + nb * 16;
                int ck = (ks * 2 + bkh) ^ (row & 7);
                ldsm_x4(bf[nb][0], bf[nb][1], bf[nb][2], bf[nb][3],
                        sb + row * 128 + ck * 16);
            }
#pragma unroll
            for (int mt = 0; mt < 4; mt++)
#pragma unroll
                for (int nt = 0; nt < 8; nt++) {
                    uint32_t b0 = bf[nt >> 1][(nt & 1) * 2 + 0];
                    uint32_t b1 = bf[nt >> 1][(nt & 1) * 2 + 1];
                    mma16816(acc[mt][nt][0], acc[mt][nt][1],
                             acc[mt][nt][2], acc[mt][nt][3],
                             af[mt][0], af[mt][1], af[mt][2], af[mt][3], b0, b1);
                }
        }
    }

    const int erow = lid >> 2;
    const int ecol = (lid & 3) * 2;
#pragma unroll
    for (int mt = 0; mt < 4; mt++) {
#pragma unroll
        for (int nt = 0; nt < 8; nt++) {
            long r0 = bm + wm + mt * 16 + erow;
            long col = bn + wn + nt * 8 + ecol;
            float2 v0 = {acc[mt][nt][0], acc[mt][nt][1]};
            float2 v1 = {acc[mt][nt][2], acc[mt][nt][3]};
            *(float2*)(C + r0 * ldc + col)       = v0;
            *(float2*)(C + (r0 + 8) * ldc + col) = v1;
        }
    }
}

// ---------------------------------------------------------------------------
// Attention stage A (HMMA, 2-term): KV_c = [Kh|Kl]^T · [Vh|Vh]  (k=128)
// ---------------------------------------------------------------------------
__global__ void __launch_bounds__(256) chunk_kv_hmma(const float* __restrict__ qkv,
                                                     float* __restrict__ kv) {
    __shared__ __align__(1024) char sm2[24576];
    const uint32_t smb = smem_u32(sm2);

    const int c = blockIdx.x, bh = blockIdx.y;
    const int b = bh / Hn, h = bh % Hn;
    const int tid = threadIdx.x;
    const int wid = tid >> 5, lid = tid & 31;
    const long t0 = (long)c * LCH;

    const float* base = qkv + ((long)b * Tn) * (3 * Cn) + h * DHn;

#pragma unroll
    for (int p = tid; p < 1024; p += 256) {
        int t = p >> 4;
        int d = (p & 15) << 2;
        const float* rowp = base + (t0 + t) * (3 * Cn);
        float4 k4 = *(const float4*)(rowp + Cn + d);
        float4 v4 = *(const float4*)(rowp + 2 * Cn + d);
        uint2 hh, ll;
        split4(k4, hh, ll);
        *(uint2*)(sm2 + offR(t, d))      = hh;
        *(uint2*)(sm2 + offR(t + 64, d)) = ll;
        *(uint2*)(sm2 + 16384 + offR(t, d)) = hi4(v4);
    }
    __syncthreads();

    const int wm = (wid & 3) * 16;
    const int wn = (wid >> 2) * 32;
    const int mat = lid >> 3, r8 = lid & 7;
    const int akr = (mat >> 1) * 8 + r8;
    const int amc = (wm >> 3) + (mat & 1);
    const int tkr = (mat & 1) * 8 + r8;
    const int tnc = mat >> 1;

    float acc[4][4];
#pragma unroll
    for (int nt = 0; nt < 4; nt++)
#pragma unroll
        for (int q = 0; q < 4; q++) acc[nt][q] = 0.f;

#pragma unroll
    for (int ks = 0; ks < 8; ks++) {
        int blk = ks >> 2;
        int kl = (ks & 3) * 16;
        int abase = blk ? 64 : 0;

        uint32_t af[4], bf[2][4];
        {
            int row = abase + kl + akr;
            ldsm_x4_t(af[0], af[1], af[2], af[3],
                      smb + (uint32_t)(row * 128 + ((amc ^ (row & 7)) << 4)));
        }
#pragma unroll
        for (int nb = 0; nb < 2; nb++) {
            int row = kl + tkr;
            int cc = (wn >> 3) + nb * 2 + tnc;
            ldsm_x4_t(bf[nb][0], bf[nb][1], bf[nb][2], bf[nb][3],
                      smb + 16384 + (uint32_t)(row * 128 + ((cc ^ (row & 7)) << 4)));
        }
#pragma unroll
        for (int nt = 0; nt < 4; nt++)
            mma16816(acc[nt][0], acc[nt][1], acc[nt][2], acc[nt][3],
                     af[0], af[1], af[2], af[3],
                     bf[nt >> 1][(nt & 1) * 2], bf[nt >> 1][(nt & 1) * 2 + 1]);
    }

    const int r = lid >> 2;
    const int cq = (lid & 3) * 2;
    float* outp = kv + ((long)(bh * NCH + c) << 12);
#pragma unroll
    for (int nt = 0; nt < 4; nt++) {
        int col = wn + nt * 8 + cq;
        float2 v0 = {acc[nt][0], acc[nt][1]};
        float2 v1 = {acc[nt][2], acc[nt][3]};
        *(float2*)(outp + (wm + r) * DHn + col)     = v0;
        *(float2*)(outp + (wm + r + 8) * DHn + col) = v1;
    }
}

// ---------------------------------------------------------------------------
// Attention stage B: exclusive prefix over chunks. grid (B*H, 16).
// ---------------------------------------------------------------------------
__global__ void __launch_bounds__(256) prefix_kernel(const float* __restrict__ kv,
                                                     float* __restrict__ s) {
    const int bh = blockIdx.x;
    const int idx = blockIdx.y * 256 + threadIdx.x;
    float S = 0.f;
#pragma unroll 4
    for (int c = 0; c < NCH; c++) {
        long base = (long)(bh * NCH + c) << 12;
        s[base + idx] = S;
        S += kv[base + idx];
    }
}

// ---------------------------------------------------------------------------
// Attention stage C (HMMA fp16 2-term); epilogue writes O hi-only.
// ---------------------------------------------------------------------------
#define QP_OFF 0
#define KP_OFF 16384
#define PP_OFF 16384
#define VP_OFF 32768
#define SP_OFF 49152
#define ATT_SMEM 65536

__global__ void __launch_bounds__(256, 2) attn_hmma(const float* __restrict__ qkv,
                                                    const float* __restrict__ s,
                                                    __half* __restrict__ ahl) {
    extern __shared__ __align__(1024) char asmem[];
    char* sm = asmem;
    const uint32_t smb = smem_u32(asmem);

    const int c = blockIdx.x, bh = blockIdx.y;
    const int b = bh / Hn, h = bh % Hn;
    const int tid = threadIdx.x;
    const int wid = tid >> 5, lid = tid & 31;
    const long t0 = (long)c * LCH;

    const float* qbase = qkv + ((long)b * Tn) * (3 * Cn) + h * DHn;
    const float* sbase = s + ((long)(bh * NCH + c) << 12);

#pragma unroll
    for (int p = tid; p < 1024; p += 256) {
        int t = p >> 4;
        int d = (p & 15) << 2;
        const float* rowp = qbase + (t0 + t) * (3 * Cn);
        float4 q4 = *(const float4*)(rowp + d);
        float4 k4 = *(const float4*)(rowp + Cn + d);
        float4 v4 = *(const float4*)(rowp + 2 * Cn + d);
        float4 s4 = *(const float4*)(sbase + t * DHn + d);

        uint2 hh, ll;
        split4(q4, hh, ll);
        *(uint2*)(sm + QP_OFF + off128(t, d))      = hh;
        *(uint2*)(sm + QP_OFF + off128(t, 64 + d)) = ll;

        uint2 kh = hi4(k4);
        *(uint2*)(sm + KP_OFF + off128(t, d))      = kh;
        *(uint2*)(sm + KP_OFF + off128(t, 64 + d)) = kh;

        uint2 vh = hi4(v4);
        *(uint2*)(sm + VP_OFF + offR(t, d))      = vh;
        *(uint2*)(sm + VP_OFF + offR(t + 64, d)) = vh;

        uint2 sh = hi4(s4);
        *(uint2*)(sm + SP_OFF + offR(t, d))      = sh;
        *(uint2*)(sm + SP_OFF + offR(t + 64, d)) = sh;
    }
    __syncthreads();

    const int wm = (wid & 3) * 16;
    const int wn = (wid >> 2) * 32;
    const int mat = lid >> 3, r8 = lid & 7;
    const int arow = wm + (mat & 1) * 8 + r8;
    const int akh = mat >> 1;
    const int bro = (mat >> 1) * 8 + r8;
    const int bkh = mat & 1;
    const int tkr = (mat & 1) * 8 + r8;
    const int tnc = mat >> 1;

    // ---- P = Q K^T (k = 128) ----
    float pac[4][4];
#pragma unroll
    for (int nt = 0; nt < 4; nt++)
#pragma unroll
        for (int q = 0; q < 4; q++) pac[nt][q] = 0.f;

#pragma unroll
    for (int ks = 0; ks < 8; ks++) {
        uint32_t af[4], bf[2][4];
        ldsm_x4(af[0], af[1], af[2], af[3],
                smb + QP_OFF + (uint32_t)(arow * 256 + (((ks * 2 + akh) ^ (arow & 7)) << 4)));
#pragma unroll
        for (int nb = 0; nb < 2; nb++) {
            int row = wn + nb * 16 + bro;
            ldsm_x4(bf[nb][0], bf[nb][1], bf[nb][2], bf[nb][3],
                    smb + KP_OFF + (uint32_t)(row * 256 + (((ks * 2 + bkh) ^ (row & 7)) << 4)));
        }
#pragma unroll
        for (int nt = 0; nt < 4; nt++)
            mma16816(pac[nt][0], pac[nt][1], pac[nt][2], pac[nt][3],
                     af[0], af[1], af[2], af[3],
                     bf[nt >> 1][(nt & 1) * 2], bf[nt >> 1][(nt & 1) * 2 + 1]);
    }

    __syncthreads();   // Kp fully consumed before Pp overwrite

    {
        const int r = lid >> 2;
        const int cq = (lid & 3) * 2;
#pragma unroll
        for (int nt = 0; nt < 4; nt++) {
            int col = wn + nt * 8 + cq;
            int row0 = wm + r, row1 = wm + r + 8;
            float c0 = (col     <= row0) ? pac[nt][0] : 0.f;
            float c1 = (col + 1 <= row0) ? pac[nt][1] : 0.f;
            float c2 = (col     <= row1) ? pac[nt][2] : 0.f;
            float c3 = (col + 1 <= row1) ? pac[nt][3] : 0.f;
            uint32_t hi, lo;
            split2(c0, c1, hi, lo);
            *(uint32_t*)(sm + PP_OFF + off128(row0, col))      = hi;
            *(uint32_t*)(sm + PP_OFF + off128(row0, 64 + col)) = lo;
            split2(c2, c3, hi, lo);
            *(uint32_t*)(sm + PP_OFF + off128(row1, col))      = hi;
            *(uint32_t*)(sm + PP_OFF + off128(row1, 64 + col)) = lo;
        }
    }
    __syncthreads();

    // ---- O = [Pp | Qp] x [Vh ; Sh]  (k = 256) ----
    float oac[4][4];
#pragma unroll
    for (int nt = 0; nt < 4; nt++)
#pragma unroll
        for (int q = 0; q < 4; q++) oac[nt][q] = 0.f;

#pragma unroll
    for (int ks = 0; ks < 16; ks++) {
        uint32_t abase = (ks < 8) ? (smb + PP_OFF) : (smb + QP_OFF);
        int ksl = ks & 7;
        uint32_t bbase = (ks < 8) ? (smb + VP_OFF) : (smb + SP_OFF);
        int krow = ksl * 16 + tkr;

        uint32_t af[4], bf[2][4];
        ldsm_x4(af[0], af[1], af[2], af[3],
                abase + (uint32_t)(arow * 256 + (((ksl * 2 + akh) ^ (arow & 7)) << 4)));
#pragma unroll
        for (int nb = 0; nb < 2; nb++) {
            int cc = (wn >> 3) + nb * 2 + tnc;
            ldsm_x4_t(bf[nb][0], bf[nb][1], bf[nb][2], bf[nb][3],
                      bbase + (uint32_t)(krow * 128 + ((cc ^ (krow & 7)) << 4)));
        }
#pragma unroll
        for (int nt = 0; nt < 4; nt++)
            mma16816(oac[nt][0], oac[nt][1], oac[nt][2], oac[nt][3],
                     af[0], af[1], af[2], af[3],
                     bf[nt >> 1][(nt & 1) * 2], bf[nt >> 1][(nt & 1) * 2 + 1]);
    }

    // ---- scale, fp16 hi-only write to g_ahl ----
    {
        const int r = lid >> 2;
        const int cq = (lid & 3) * 2;
        __half* abase = ahl + ((long)b * Tn + t0) * KP + h * DHn;
#pragma unroll
        for (int nt = 0; nt < 4; nt++) {
            int dg = wn + nt * 8 + cq;
            __half2 h0 = __floats2half2_rn(oac[nt][0] * SCALE_F, oac[nt][1] * SCALE_F);
            __half2 h1 = __floats2half2_rn(oac[nt][2] * SCALE_F, oac[nt][3] * SCALE_F);
            *(uint32_t*)(abase + (long)(wm + r) * KP + dg)     = *(uint32_t*)&h0;
            *(uint32_t*)(abase + (long)(wm + r + 8) * KP + dg) = *(uint32_t*)&h1;
        }
    }
}

// ---------------------------------------------------------------------------
extern "C" void kernel_launch(void* const* d_in, const int* in_sizes, int n_in,
                              void* d_out, int out_size) {
    const float* x    = (const float*)d_in[0];
    const float* Wqkv = (const float*)d_in[1];
    const float* Wout = (const float*)d_in[2];
    float* out = (float*)d_out;

    float *qkv_p, *kv_p, *s_p;
    __half *xhl_p, *ahl_p, *wq_p, *wo_p;
    cudaGetSymbolAddress((void**)&qkv_p, g_qkv);
    cudaGetSymbolAddress((void**)&kv_p, g_kv);
    cudaGetSymbolAddress((void**)&s_p, g_s);
    cudaGetSymbolAddress((void**)&xhl_p, g_xhl);
    cudaGetSymbolAddress((void**)&ahl_p, g_ahl);
    cudaGetSymbolAddress((void**)&wq_p, g_wqkv);
    cudaGetSymbolAddress((void**)&wo_p, g_wout);

    const int M = Bn * Tn;
    const int gemm_smem = NSTG * STG_B;          // 98304
    cudaFuncSetAttribute(gemm_hmma, cudaFuncAttributeMaxDynamicSharedMemorySize, gemm_smem);
    cudaFuncSetAttribute(attn_hmma, cudaFuncAttributeMaxDynamicSharedMemorySize, ATT_SMEM);

    // merged hi-only converts (one launch)
    {
        int total = NX + NWQ + NWO;
        cvt_all<<<(total + 255) / 256, 256>>>(x, Wqkv, Wout, xhl_p, wq_p, wo_p);
    }

    // GEMM1: qkv = xh @ Wqkv_h^T  (K'=1024, N=3072)
    {
        dim3 grid(M / 128, 3 * Cn / 128);
        gemm_hmma<<<grid, 128, gemm_smem>>>(xhl_p, wq_p, qkv_p, 3 * Cn, Cn);
    }

    // attention: HMMA chunk KV -> prefix -> HMMA per-chunk output
    {
        dim3 gkv(NCH, Bn * Hn);
        chunk_kv_hmma<<<gkv, 256>>>(qkv_p, kv_p);
        dim3 gpre(Bn * Hn, 16);
        prefix_kernel<<<gpre, 256>>>(kv_p, s_p);
        attn_hmma<<<gkv, 256, ATT_SMEM>>>(qkv_p, s_p, ahl_p);
    }

    // GEMM2: out = attn_h @ Wout_h^T  (K'=1024)
    {
        dim3 grid(M / 128, Cn / 128);
        gemm_hmma<<<grid, 128, gemm_smem>>>(ahl_p, wo_p, out, Cn, Cn);
    }
}

// round 17
// speedup vs baseline: 1.0799x; 1.0077x over previous
#include <cuda_runtime.h>
#include <cuda_fp16.h>
#include <cstdint>

#define Bn 4
#define Tn 2048
#define Cn 1024
#define Hn 16
#define DHn 64
#define SCALE_F 0.125f
#define KP 2048                 // row stride of fp16 buffers (hi half used)
#define NCH 32
#define LCH 64

// ---------------- scratch (__device__ globals) ------------------------------
__device__ float  g_qkv[Bn * Tn * 3 * Cn];    // [8192,3072] fp32
__device__ __half g_xhl[Bn * Tn * KP];        // x    -> [hi|-]
__device__ __half g_ahl[Bn * Tn * KP];        // attn -> [hi|-]
__device__ __half g_wqkv[3 * Cn * KP];        // Wqkv -> [hi|-]
__device__ __half g_wout[Cn * KP];            // Wout -> [hi|-]
__device__ float  g_kv[Bn * Hn * NCH * DHn * DHn];
__device__ __half g_s [Bn * Hn * NCH * DHn * DHn];   // fp16 prefix (hi-rounded)

// ---------------- helpers ---------------------------------------------------
__device__ __forceinline__ uint32_t smem_u32(const void* p) {
    uint32_t a;
    asm("{ .reg .u64 t; cvta.to.shared.u64 t, %1; cvt.u32.u64 %0, t; }" : "=r"(a) : "l"(p));
    return a;
}
__device__ __forceinline__ void ldsm_x4(uint32_t& r0, uint32_t& r1, uint32_t& r2,
                                        uint32_t& r3, uint32_t addr) {
    asm volatile("ldmatrix.sync.aligned.m8n8.x4.shared.b16 {%0,%1,%2,%3}, [%4];"
                 : "=r"(r0), "=r"(r1), "=r"(r2), "=r"(r3) : "r"(addr));
}
__device__ __forceinline__ void ldsm_x4_t(uint32_t& r0, uint32_t& r1, uint32_t& r2,
                                          uint32_t& r3, uint32_t addr) {
    asm volatile("ldmatrix.sync.aligned.m8n8.x4.trans.shared.b16 {%0,%1,%2,%3}, [%4];"
                 : "=r"(r0), "=r"(r1), "=r"(r2), "=r"(r3) : "r"(addr));
}
__device__ __forceinline__ void mma16816(float& d0, float& d1, float& d2, float& d3,
                                         uint32_t a0, uint32_t a1, uint32_t a2, uint32_t a3,
                                         uint32_t b0, uint32_t b1) {
    asm volatile(
        "mma.sync.aligned.m16n8k16.row.col.f32.f16.f16.f32 "
        "{%0,%1,%2,%3},{%4,%5,%6,%7},{%8,%9},{%0,%1,%2,%3};"
        : "+f"(d0), "+f"(d1), "+f"(d2), "+f"(d3)
        : "r"(a0), "r"(a1), "r"(a2), "r"(a3), "r"(b0), "r"(b1));
}

__device__ __forceinline__ void split4(float4 v, uint2& hh, uint2& ll) {
    __half2 h0 = __floats2half2_rn(v.x, v.y);
    __half2 h1 = __floats2half2_rn(v.z, v.w);
    float rx = v.x - __half2float(__low2half(h0));
    float ry = v.y - __half2float(__high2half(h0));
    float rz = v.z - __half2float(__low2half(h1));
    float rw = v.w - __half2float(__high2half(h1));
    __half2 l0 = __floats2half2_rn(rx, ry);
    __half2 l1 = __floats2half2_rn(rz, rw);
    hh.x = *(uint32_t*)&h0; hh.y = *(uint32_t*)&h1;
    ll.x = *(uint32_t*)&l0; ll.y = *(uint32_t*)&l1;
}
__device__ __forceinline__ uint2 hi4(float4 v) {
    __half2 h0 = __floats2half2_rn(v.x, v.y);
    __half2 h1 = __floats2half2_rn(v.z, v.w);
    uint2 r; r.x = *(uint32_t*)&h0; r.y = *(uint32_t*)&h1;
    return r;
}
__device__ __forceinline__ void split2(float a, float b, uint32_t& hi, uint32_t& lo) {
    __half2 h = __floats2half2_rn(a, b);
    float ra = a - __half2float(__low2half(h));
    float rb = b - __half2float(__high2half(h));
    __half2 l = __floats2half2_rn(ra, rb);
    hi = *(uint32_t*)&h; lo = *(uint32_t*)&l;
}

__device__ __forceinline__ uint32_t offR(int row, int d) {        // 128B rows
    return (uint32_t)(row * 128 + (((d >> 3) ^ (row & 7)) << 4) + ((d & 7) << 1));
}
__device__ __forceinline__ uint32_t off128(int row, int kpos) {   // 256B rows
    return (uint32_t)(row * 256 + (((kpos >> 3) ^ (row & 7)) << 4) + ((kpos & 7) << 1));
}

// ---------------------------------------------------------------------------
// Merged hi-only convert of x, Wqkv, Wout (one launch).
// ---------------------------------------------------------------------------
#define NX  (Bn * Tn * Cn / 4)
#define NWQ (3 * Cn * Cn / 4)
#define NWO (Cn * Cn / 4)

__global__ void __launch_bounds__(256) cvt_all(const float* __restrict__ x,
                                               const float* __restrict__ wq,
                                               const float* __restrict__ wo,
                                               __half* __restrict__ xo,
                                               __half* __restrict__ wqo,
                                               __half* __restrict__ woo) {
    int idx = blockIdx.x * 256 + threadIdx.x;
    const float* in;
    __half* out;
    if (idx < NX) {
        in = x; out = xo;
    } else if (idx < NX + NWQ) {
        idx -= NX; in = wq; out = wqo;
    } else {
        idx -= NX + NWQ;
        if (idx >= NWO) return;
        in = wo; out = woo;
    }
    int per_row = Cn >> 2;
    int r = idx / per_row;
    int k = (idx - r * per_row) << 2;
    float4 v = *(const float4*)(in + (long)r * Cn + k);
    *(uint2*)(out + (long)r * KP + k) = hi4(v);
}

// ---------------------------------------------------------------------------
// HMMA fp16 NT GEMM: Kdim/ldc runtime, fp32 out.
// 128x128 CTA, 4 warps 64x64, 3-stage cp.async, 2 CTAs/SM.
// ---------------------------------------------------------------------------
#define KC 64
#define STG_B 32768
#define NSTG 3

__global__ void __launch_bounds__(128, 2) gemm_hmma(const __half* __restrict__ A,
                                                    const __half* __restrict__ Bw,
                                                    float* __restrict__ C,
                                                    int ldc, int Kdim) {
    extern __shared__ __align__(1024) char dsm[];
    const uint32_t smem0 = smem_u32(dsm);
    const int NIT = Kdim >> 6;

    const int tid = threadIdx.x;
    const int wid = tid >> 5, lid = tid & 31;
    const int bm = blockIdx.x * 128;
    const int bn = blockIdx.y * 128;
    const int wm = (wid & 1) * 64;
    const int wn = (wid >> 1) * 64;

    const char* gsrc[16];
    uint32_t sdst[16];
#pragma unroll
    for (int i = 0; i < 16; i++) {
        int c = tid + i * 128;
        int row = c >> 3;
        int ck = c & 7;
        const __half* base =
            (row < 128) ? (A + (long)(bm + row) * KP)
                        : (Bw + (long)(bn + row - 128) * KP);
        gsrc[i] = (const char*)base + ck * 16;
        sdst[i] = row * 128 + ((ck ^ (row & 7)) * 16);
    }

    auto load_stage = [&](int j) {
        uint32_t sb = smem0 + (j % NSTG) * STG_B;
        long koff = (long)j * (KC * 2);
#pragma unroll
        for (int i = 0; i < 16; i++) {
            asm volatile("cp.async.cg.shared.global [%0], [%1], 16;"
                         :: "r"(sb + sdst[i]), "l"(gsrc[i] + koff));
        }
        asm volatile("cp.async.commit_group;" ::: "memory");
    };

    float acc[4][8][4];
#pragma unroll
    for (int mt = 0; mt < 4; mt++)
#pragma unroll
        for (int nt = 0; nt < 8; nt++)
#pragma unroll
            for (int q = 0; q < 4; q++) acc[mt][nt][q] = 0.f;

    load_stage(0);
    load_stage(1);

    const int mat = lid >> 3, r8 = lid & 7;
    const int arow = wm + (mat & 1) * 8 + r8;
    const int brow = 128 + wn + (mat >> 1) * 8 + r8;
    const int akh = mat >> 1;
    const int bkh = mat & 1;

    for (int it = 0; it < NIT; it++) {
        if (it + 1 < NIT) {
            asm volatile("cp.async.wait_group 1;" ::: "memory");
        } else {
            asm volatile("cp.async.wait_group 0;" ::: "memory");
        }
        __syncthreads();
        if (it + 2 < NIT) load_stage(it + 2);

        uint32_t sb = smem0 + (it % NSTG) * STG_B;
#pragma unroll
        for (int ks = 0; ks < 4; ks++) {
            uint32_t af[4][4], bf[4][4];
#pragma unroll
            for (int mt = 0; mt < 4; mt++) {
                int row = arow + mt * 16;
                int ck = (ks * 2 + akh) ^ (row & 7);
                ldsm_x4(af[mt][0], af[mt][1], af[mt][2], af[mt][3],
                        sb + row * 128 + ck * 16);
            }
#pragma unroll
            for (int nb = 0; nb < 4; nb++) {
                int row = brow + nb * 16;
                int ck = (ks * 2 + bkh) ^ (row & 7);
                ldsm_x4(bf[nb][0], bf[nb][1], bf[nb][2], bf[nb][3],
                        sb + row * 128 + ck * 16);
            }
#pragma unroll
            for (int mt = 0; mt < 4; mt++)
#pragma unroll
                for (int nt = 0; nt < 8; nt++) {
                    uint32_t b0 = bf[nt >> 1][(nt & 1) * 2 + 0];
                    uint32_t b1 = bf[nt >> 1][(nt & 1) * 2 + 1];
                    mma16816(acc[mt][nt][0], acc[mt][nt][1],
                             acc[mt][nt][2], acc[mt][nt][3],
                             af[mt][0], af[mt][1], af[mt][2], af[mt][3], b0, b1);
                }
        }
    }

    const int erow = lid >> 2;
    const int ecol = (lid & 3) * 2;
#pragma unroll
    for (int mt = 0; mt < 4; mt++) {
#pragma unroll
        for (int nt = 0; nt < 8; nt++) {
            long r0 = bm + wm + mt * 16 + erow;
            long col = bn + wn + nt * 8 + ecol;
            float2 v0 = {acc[mt][nt][0], acc[mt][nt][1]};
            float2 v1 = {acc[mt][nt][2], acc[mt][nt][3]};
            *(float2*)(C + r0 * ldc + col)       = v0;
            *(float2*)(C + (r0 + 8) * ldc + col) = v1;
        }
    }
}

// ---------------------------------------------------------------------------
// Attention stage A (HMMA, 2-term): KV_c = [Kh|Kl]^T · [Vh|Vh]  (k=128)
// ---------------------------------------------------------------------------
__global__ void __launch_bounds__(256) chunk_kv_hmma(const float* __restrict__ qkv,
                                                     float* __restrict__ kv) {
    __shared__ __align__(1024) char sm2[24576];
    const uint32_t smb = smem_u32(sm2);

    const int c = blockIdx.x, bh = blockIdx.y;
    const int b = bh / Hn, h = bh % Hn;
    const int tid = threadIdx.x;
    const int wid = tid >> 5, lid = tid & 31;
    const long t0 = (long)c * LCH;

    const float* base = qkv + ((long)b * Tn) * (3 * Cn) + h * DHn;

#pragma unroll
    for (int p = tid; p < 1024; p += 256) {
        int t = p >> 4;
        int d = (p & 15) << 2;
        const float* rowp = base + (t0 + t) * (3 * Cn);
        float4 k4 = *(const float4*)(rowp + Cn + d);
        float4 v4 = *(const float4*)(rowp + 2 * Cn + d);
        uint2 hh, ll;
        split4(k4, hh, ll);
        *(uint2*)(sm2 + offR(t, d))      = hh;
        *(uint2*)(sm2 + offR(t + 64, d)) = ll;
        *(uint2*)(sm2 + 16384 + offR(t, d)) = hi4(v4);
    }
    __syncthreads();

    const int wm = (wid & 3) * 16;
    const int wn = (wid >> 2) * 32;
    const int mat = lid >> 3, r8 = lid & 7;
    const int akr = (mat >> 1) * 8 + r8;
    const int amc = (wm >> 3) + (mat & 1);
    const int tkr = (mat & 1) * 8 + r8;
    const int tnc = mat >> 1;

    float acc[4][4];
#pragma unroll
    for (int nt = 0; nt < 4; nt++)
#pragma unroll
        for (int q = 0; q < 4; q++) acc[nt][q] = 0.f;

#pragma unroll
    for (int ks = 0; ks < 8; ks++) {
        int blk = ks >> 2;
        int kl = (ks & 3) * 16;
        int abase = blk ? 64 : 0;

        uint32_t af[4], bf[2][4];
        {
            int row = abase + kl + akr;
            ldsm_x4_t(af[0], af[1], af[2], af[3],
                      smb + (uint32_t)(row * 128 + ((amc ^ (row & 7)) << 4)));
        }
#pragma unroll
        for (int nb = 0; nb < 2; nb++) {
            int row = kl + tkr;
            int cc = (wn >> 3) + nb * 2 + tnc;
            ldsm_x4_t(bf[nb][0], bf[nb][1], bf[nb][2], bf[nb][3],
                      smb + 16384 + (uint32_t)(row * 128 + ((cc ^ (row & 7)) << 4)));
        }
#pragma unroll
        for (int nt = 0; nt < 4; nt++)
            mma16816(acc[nt][0], acc[nt][1], acc[nt][2], acc[nt][3],
                     af[0], af[1], af[2], af[3],
                     bf[nt >> 1][(nt & 1) * 2], bf[nt >> 1][(nt & 1) * 2 + 1]);
    }

    const int r = lid >> 2;
    const int cq = (lid & 3) * 2;
    float* outp = kv + ((long)(bh * NCH + c) << 12);
#pragma unroll
    for (int nt = 0; nt < 4; nt++) {
        int col = wn + nt * 8 + cq;
        float2 v0 = {acc[nt][0], acc[nt][1]};
        float2 v1 = {acc[nt][2], acc[nt][3]};
        *(float2*)(outp + (wm + r) * DHn + col)     = v0;
        *(float2*)(outp + (wm + r + 8) * DHn + col) = v1;
    }
}

// ---------------------------------------------------------------------------
// Attention stage B: exclusive prefix over chunks; fp32 accumulate,
// fp16 (hi-rounded) store — bit-identical to attn's previous hi4(s).
// grid (B*H, 16).
// ---------------------------------------------------------------------------
__global__ void __launch_bounds__(256) prefix_kernel(const float* __restrict__ kv,
                                                     __half* __restrict__ s) {
    const int bh = blockIdx.x;
    const int idx = blockIdx.y * 256 + threadIdx.x;
    float S = 0.f;
#pragma unroll 4
    for (int c = 0; c < NCH; c++) {
        long base = (long)(bh * NCH + c) << 12;
        s[base + idx] = __float2half_rn(S);
        S += kv[base + idx];
    }
}

// ---------------------------------------------------------------------------
// Attention stage C (HMMA fp16 2-term); S read as fp16; O hi-only out.
// ---------------------------------------------------------------------------
#define QP_OFF 0
#define KP_OFF 16384
#define PP_OFF 16384
#define VP_OFF 32768
#define SP_OFF 49152
#define ATT_SMEM 65536

__global__ void __launch_bounds__(256, 2) attn_hmma(const float* __restrict__ qkv,
                                                    const __half* __restrict__ s,
                                                    __half* __restrict__ ahl) {
    extern __shared__ __align__(1024) char asmem[];
    char* sm = asmem;
    const uint32_t smb = smem_u32(asmem);

    const int c = blockIdx.x, bh = blockIdx.y;
    const int b = bh / Hn, h = bh % Hn;
    const int tid = threadIdx.x;
    const int wid = tid >> 5, lid = tid & 31;
    const long t0 = (long)c * LCH;

    const float* qbase = qkv + ((long)b * Tn) * (3 * Cn) + h * DHn;
    const __half* sbase = s + ((long)(bh * NCH + c) << 12);

#pragma unroll
    for (int p = tid; p < 1024; p += 256) {
        int t = p >> 4;
        int d = (p & 15) << 2;
        const float* rowp = qbase + (t0 + t) * (3 * Cn);
        float4 q4 = *(const float4*)(rowp + d);
        float4 k4 = *(const float4*)(rowp + Cn + d);
        float4 v4 = *(const float4*)(rowp + 2 * Cn + d);
        uint2 sh = *(const uint2*)(sbase + t * DHn + d);

        uint2 hh, ll;
        split4(q4, hh, ll);
        *(uint2*)(sm + QP_OFF + off128(t, d))      = hh;
        *(uint2*)(sm + QP_OFF + off128(t, 64 + d)) = ll;

        uint2 kh = hi4(k4);
        *(uint2*)(sm + KP_OFF + off128(t, d))      = kh;
        *(uint2*)(sm + KP_OFF + off128(t, 64 + d)) = kh;

        uint2 vh = hi4(v4);
        *(uint2*)(sm + VP_OFF + offR(t, d))      = vh;
        *(uint2*)(sm + VP_OFF + offR(t + 64, d)) = vh;

        *(uint2*)(sm + SP_OFF + offR(t, d))      = sh;
        *(uint2*)(sm + SP_OFF + offR(t + 64, d)) = sh;
    }
    __syncthreads();

    const int wm = (wid & 3) * 16;
    const int wn = (wid >> 2) * 32;
    const int mat = lid >> 3, r8 = lid & 7;
    const int arow = wm + (mat & 1) * 8 + r8;
    const int akh = mat >> 1;
    const int bro = (mat >> 1) * 8 + r8;
    const int bkh = mat & 1;
    const int tkr = (mat & 1) * 8 + r8;
    const int tnc = mat >> 1;

    // ---- P = Q K^T (k = 128) ----
    float pac[4][4];
#pragma unroll
    for (int nt = 0; nt < 4; nt++)
#pragma unroll
        for (int q = 0; q < 4; q++) pac[nt][q] = 0.f;

#pragma unroll
    for (int ks = 0; ks < 8; ks++) {
        uint32_t af[4], bf[2][4];
        ldsm_x4(af[0], af[1], af[2], af[3],
                smb + QP_OFF + (uint32_t)(arow * 256 + (((ks * 2 + akh) ^ (arow & 7)) << 4)));
#pragma unroll
        for (int nb = 0; nb < 2; nb++) {
            int row = wn + nb * 16 + bro;
            ldsm_x4(bf[nb][0], bf[nb][1], bf[nb][2], bf[nb][3],
                    smb + KP_OFF + (uint32_t)(row * 256 + (((ks * 2 + bkh) ^ (row & 7)) << 4)));
        }
#pragma unroll
        for (int nt = 0; nt < 4; nt++)
            mma16816(pac[nt][0], pac[nt][1], pac[nt][2], pac[nt][3],
                     af[0], af[1], af[2], af[3],
                     bf[nt >> 1][(nt & 1) * 2], bf[nt >> 1][(nt & 1) * 2 + 1]);
    }

    __syncthreads();   // Kp fully consumed before Pp overwrite

    {
        const int r = lid >> 2;
        const int cq = (lid & 3) * 2;
#pragma unroll
        for (int nt = 0; nt < 4; nt++) {
            int col = wn + nt * 8 + cq;
            int row0 = wm + r, row1 = wm + r + 8;
            float c0 = (col     <= row0) ? pac[nt][0] : 0.f;
            float c1 = (col + 1 <= row0) ? pac[nt][1] : 0.f;
            float c2 = (col     <= row1) ? pac[nt][2] : 0.f;
            float c3 = (col + 1 <= row1) ? pac[nt][3] : 0.f;
            uint32_t hi, lo;
            split2(c0, c1, hi, lo);
            *(uint32_t*)(sm + PP_OFF + off128(row0, col))      = hi;
            *(uint32_t*)(sm + PP_OFF + off128(row0, 64 + col)) = lo;
            split2(c2, c3, hi, lo);
            *(uint32_t*)(sm + PP_OFF + off128(row1, col))      = hi;
            *(uint32_t*)(sm + PP_OFF + off128(row1, 64 + col)) = lo;
        }
    }
    __syncthreads();

    // ---- O = [Pp | Qp] x [Vh ; Sh]  (k = 256) ----
    float oac[4][4];
#pragma unroll
    for (int nt = 0; nt < 4; nt++)
#pragma unroll
        for (int q = 0; q < 4; q++) oac[nt][q] = 0.f;

#pragma unroll
    for (int ks = 0; ks < 16; ks++) {
        uint32_t abase = (ks < 8) ? (smb + PP_OFF) : (smb + QP_OFF);
        int ksl = ks & 7;
        uint32_t bbase = (ks < 8) ? (smb + VP_OFF) : (smb + SP_OFF);
        int krow = ksl * 16 + tkr;

        uint32_t af[4], bf[2][4];
        ldsm_x4(af[0], af[1], af[2], af[3],
                abase + (uint32_t)(arow * 256 + (((ksl * 2 + akh) ^ (arow & 7)) << 4)));
#pragma unroll
        for (int nb = 0; nb < 2; nb++) {
            int cc = (wn >> 3) + nb * 2 + tnc;
            ldsm_x4_t(bf[nb][0], bf[nb][1], bf[nb][2], bf[nb][3],
                      bbase + (uint32_t)(krow * 128 + ((cc ^ (krow & 7)) << 4)));
        }
#pragma unroll
        for (int nt = 0; nt < 4; nt++)
            mma16816(oac[nt][0], oac[nt][1], oac[nt][2], oac[nt][3],
                     af[0], af[1], af[2], af[3],
                     bf[nt >> 1][(nt & 1) * 2], bf[nt >> 1][(nt & 1) * 2 + 1]);
    }

    // ---- scale, fp16 hi-only write to g_ahl ----
    {
        const int r = lid >> 2;
        const int cq = (lid & 3) * 2;
        __half* abase = ahl + ((long)b * Tn + t0) * KP + h * DHn;
#pragma unroll
        for (int nt = 0; nt < 4; nt++) {
            int dg = wn + nt * 8 + cq;
            __half2 h0 = __floats2half2_rn(oac[nt][0] * SCALE_F, oac[nt][1] * SCALE_F);
            __half2 h1 = __floats2half2_rn(oac[nt][2] * SCALE_F, oac[nt][3] * SCALE_F);
            *(uint32_t*)(abase + (long)(wm + r) * KP + dg)     = *(uint32_t*)&h0;
            *(uint32_t*)(abase + (long)(wm + r + 8) * KP + dg) = *(uint32_t*)&h1;
        }
    }
}

// ---------------------------------------------------------------------------
extern "C" void kernel_launch(void* const* d_in, const int* in_sizes, int n_in,
                              void* d_out, int out_size) {
    const float* x    = (const float*)d_in[0];
    const float* Wqkv = (const float*)d_in[1];
    const float* Wout = (const float*)d_in[2];
    float* out = (float*)d_out;

    float *qkv_p, *kv_p;
    __half *s_p, *xhl_p, *ahl_p, *wq_p, *wo_p;
    cudaGetSymbolAddress((void**)&qkv_p, g_qkv);
    cudaGetSymbolAddress((void**)&kv_p, g_kv);
    cudaGetSymbolAddress((void**)&s_p, g_s);
    cudaGetSymbolAddress((void**)&xhl_p, g_xhl);
    cudaGetSymbolAddress((void**)&ahl_p, g_ahl);
    cudaGetSymbolAddress((void**)&wq_p, g_wqkv);
    cudaGetSymbolAddress((void**)&wo_p, g_wout);

    const int M = Bn * Tn;
    const int gemm_smem = NSTG * STG_B;          // 98304
    cudaFuncSetAttribute(gemm_hmma, cudaFuncAttributeMaxDynamicSharedMemorySize, gemm_smem);
    cudaFuncSetAttribute(attn_hmma, cudaFuncAttributeMaxDynamicSharedMemorySize, ATT_SMEM);

    // merged hi-only converts (one launch)
    {
        int total = NX + NWQ + NWO;
        cvt_all<<<(total + 255) / 256, 256>>>(x, Wqkv, Wout, xhl_p, wq_p, wo_p);
    }

    // GEMM1: qkv = xh @ Wqkv_h^T  (K'=1024, N=3072)
    {
        dim3 grid(M / 128, 3 * Cn / 128);
        gemm_hmma<<<grid, 128, gemm_smem>>>(xhl_p, wq_p, qkv_p, 3 * Cn, Cn);
    }

    // attention: HMMA chunk KV -> fp16 prefix -> HMMA per-chunk output
    {
        dim3 gkv(NCH, Bn * Hn);
        chunk_kv_hmma<<<gkv, 256>>>(qkv_p, kv_p);
        dim3 gpre(Bn * Hn, 16);
        prefix_kernel<<<gpre, 256>>>(kv_p, s_p);
        attn_hmma<<<gkv, 256, ATT_SMEM>>>(qkv_p, s_p, ahl_p);
    }

    // GEMM2: out = attn_h @ Wout_h^T  (K'=1024)
    {
        dim3 grid(M / 128, Cn / 128);
        gemm_hmma<<<grid, 128, gemm_smem>>>(ahl_p, wo_p, out, Cn, Cn);
    }
}